// round 12
// baseline (speedup 1.0000x reference)
#include <cuda_runtime.h>
#include <cuda_fp16.h>
#include <math.h>
#include <stdint.h>

#define BB 32
#define NN 1024
#define DD 128
#define HH 128
#define MNEG 100.0f

#define KT 32
#define NTILES (NN / KT)

// ---- proj smem layout (bytes) ----
#define PX_STRIDE 132
#define PW_STRIDE 136
#define PSM_X  0
#define PSM_W0 33792
#define PSM_W1 68608
#define PSM_TOTAL 103424

// ---- attn smem layout (bytes). K/V rows: 136 halfs = 272B (conflict-free) ----
#define KS2 136
#define PS2 40
#define SM_K0  0                       // 32 x 272B = 8704
#define SM_K1  8704
#define SM_V0  17408
#define SM_V1  26112
#define SM_P   34816                   // 64 x 80B = 5120
#define SM_TOTAL 39936

// Projected q/k/v in fp16 (natural [B][N][H] layout).
__device__ __align__(16) __half g_q[BB * NN * HH];
__device__ __align__(16) __half g_k[BB * NN * HH];
__device__ __align__(16) __half g_v[BB * NN * HH];

__device__ __forceinline__ unsigned tf32u(float x) {
    unsigned u;
    asm("cvt.rna.tf32.f32 %0, %1;" : "=r"(u) : "f"(x));
    return u;
}

__device__ __forceinline__ uint32_t smem_u32(const void* p) {
    uint32_t a;
    asm("{ .reg .u64 t; cvta.to.shared.u64 t, %1; cvt.u32.u64 %0, t; }" : "=r"(a) : "l"(p));
    return a;
}

#define CP_ASYNC16(dst_u32, src_ptr) \
    asm volatile("cp.async.cg.shared.global [%0], [%1], 16;" \
                 :: "r"(dst_u32), "l"(src_ptr) : "memory")
#define CP_COMMIT() asm volatile("cp.async.commit_group;" ::: "memory")
#define CP_WAIT0()  asm volatile("cp.async.wait_group 0;" ::: "memory")
#define CP_WAIT1()  asm volatile("cp.async.wait_group 1;" ::: "memory")

#define LDSM_X4(r0, r1, r2, r3, addr) \
    asm volatile("ldmatrix.sync.aligned.m8n8.x4.shared.b16 {%0,%1,%2,%3}, [%4];" \
                 : "=r"(r0), "=r"(r1), "=r"(r2), "=r"(r3) : "r"(addr))
#define LDSM_X4_T(r0, r1, r2, r3, addr) \
    asm volatile("ldmatrix.sync.aligned.m8n8.x4.trans.shared.b16 {%0,%1,%2,%3}, [%4];" \
                 : "=r"(r0), "=r"(r1), "=r"(r2), "=r"(r3) : "r"(addr))

__device__ __forceinline__ void mma_f16(float* cc,
                                        unsigned a0, unsigned a1, unsigned a2, unsigned a3,
                                        unsigned b0, unsigned b1) {
    asm volatile(
        "mma.sync.aligned.m16n8k16.row.col.f32.f16.f16.f32 "
        "{%0,%1,%2,%3}, {%4,%5,%6,%7}, {%8,%9}, {%0,%1,%2,%3};\n"
        : "+f"(cc[0]), "+f"(cc[1]), "+f"(cc[2]), "+f"(cc[3])
        : "r"(a0), "r"(a1), "r"(a2), "r"(a3), "r"(b0), "r"(b1));
}

__device__ __forceinline__ void mma_tf32(float* cc,
                                         unsigned a0, unsigned a1, unsigned a2, unsigned a3,
                                         unsigned b0, unsigned b1) {
    asm volatile(
        "mma.sync.aligned.m16n8k8.row.col.f32.tf32.tf32.f32 "
        "{%0,%1,%2,%3}, {%4,%5,%6,%7}, {%8,%9}, {%0,%1,%2,%3};\n"
        : "+f"(cc[0]), "+f"(cc[1]), "+f"(cc[2]), "+f"(cc[3])
        : "r"(a0), "r"(a1), "r"(a2), "r"(a3), "r"(b0), "r"(b1));
}

// ---------------------------------------------------------------------------
// Phase 1: q/k/v = relu(x @ W + b) in tf32 MMA, stored as fp16. (unchanged)
// ---------------------------------------------------------------------------
__global__ __launch_bounds__(128, 3) void proj_kernel(
    const float* __restrict__ x,
    const float* __restrict__ Wv, const float* __restrict__ bv,
    const float* __restrict__ Wk, const float* __restrict__ bk,
    const float* __restrict__ Wq, const float* __restrict__ bq)
{
    extern __shared__ char smem[];
    const uint32_t sb = smem_u32(smem);
    float* Xs = (float*)(smem + PSM_X);
    __shared__ float bs3[3][HH];

    const int tid = threadIdx.x;
    const int lane = tid & 31, w = tid >> 5, g = lane >> 2, c = lane & 3;
    const int row0 = blockIdx.x * 64;

    const float* const wp3[3] = {Wv, Wk, Wq};
    __half* const op3[3] = {g_v, g_k, g_q};

    {
        const char* xg = (const char*)(x + (size_t)row0 * DD);
        const char* wsrc = (const char*)Wv;
        #pragma unroll
        for (int i = 0; i < 16; i++) {
            int idx = tid + i * 128;
            int r = idx >> 5, c16 = idx & 31;
            CP_ASYNC16(sb + PSM_X + (uint32_t)(r * (PX_STRIDE * 4) + c16 * 16), xg + idx * 16);
            CP_ASYNC16(sb + PSM_W0 + (uint32_t)(r * (PW_STRIDE * 4) + c16 * 16), wsrc + idx * 16);
        }
        CP_COMMIT();
    }
    {
        const char* wsrc = (const char*)(Wv + 64 * HH);
        #pragma unroll
        for (int i = 0; i < 16; i++) {
            int idx = tid + i * 128;
            int r = idx >> 5, c16 = idx & 31;
            CP_ASYNC16(sb + PSM_W1 + (uint32_t)(r * (PW_STRIDE * 4) + c16 * 16), wsrc + idx * 16);
        }
        CP_COMMIT();
    }

    if (tid < HH) {
        bs3[0][tid] = bv[tid];
        bs3[1][tid] = bk[tid];
        bs3[2][tid] = bq[tid];
    }

    const int rb = w * 16 + g;
    unsigned xa[16][4];
    float acc[16][4];

    for (int p = 0; p < 6; p++) {
        const int wi = p >> 1, h = p & 1;
        if (p >= 4) CP_WAIT0(); else CP_WAIT1();
        __syncthreads();

        if (p == 0) {
            #pragma unroll
            for (int kk = 0; kk < 16; kk++) {
                xa[kk][0] = tf32u(Xs[rb * PX_STRIDE + kk * 8 + c]);
                xa[kk][1] = tf32u(Xs[(rb + 8) * PX_STRIDE + kk * 8 + c]);
                xa[kk][2] = tf32u(Xs[rb * PX_STRIDE + kk * 8 + c + 4]);
                xa[kk][3] = tf32u(Xs[(rb + 8) * PX_STRIDE + kk * 8 + c + 4]);
            }
        }
        if (h == 0) {
            #pragma unroll
            for (int nb = 0; nb < 16; nb++)
                acc[nb][0] = acc[nb][1] = acc[nb][2] = acc[nb][3] = 0.f;
        }

        const float* Wb = (const float*)(smem + ((p & 1) ? PSM_W1 : PSM_W0));
        #pragma unroll
        for (int nb = 0; nb < 16; nb++) {
            #pragma unroll
            for (int k2 = 0; k2 < 8; k2++) {
                int kk = h * 8 + k2;
                unsigned b0 = tf32u(Wb[(k2 * 8 + c) * PW_STRIDE + nb * 8 + g]);
                unsigned b1 = tf32u(Wb[(k2 * 8 + c + 4) * PW_STRIDE + nb * 8 + g]);
                mma_tf32(acc[nb], xa[kk][0], xa[kk][1], xa[kk][2], xa[kk][3], b0, b1);
            }
        }
        __syncthreads();

        if (p + 2 < 6) {
            const int pw = p + 2;
            const char* wsrc = (const char*)(wp3[pw >> 1] + (pw & 1) * 64 * HH);
            const uint32_t dst = sb + ((p & 1) ? PSM_W1 : PSM_W0);
            #pragma unroll
            for (int i = 0; i < 16; i++) {
                int idx = tid + i * 128;
                int r = idx >> 5, c16 = idx & 31;
                CP_ASYNC16(dst + (uint32_t)(r * (PW_STRIDE * 4) + c16 * 16), wsrc + idx * 16);
            }
            CP_COMMIT();
        }

        if (h == 1) {
            __half* outp = op3[wi];
            #pragma unroll
            for (int nb = 0; nb < 16; nb++) {
                int col = nb * 8 + 2 * c;
                float bb0 = bs3[wi][col], bb1 = bs3[wi][col + 1];
                half2 h0 = __floats2half2_rn(fmaxf(acc[nb][0] + bb0, 0.f),
                                             fmaxf(acc[nb][1] + bb1, 0.f));
                half2 h1 = __floats2half2_rn(fmaxf(acc[nb][2] + bb0, 0.f),
                                             fmaxf(acc[nb][3] + bb1, 0.f));
                *(half2*)&outp[(size_t)(row0 + rb) * HH + col] = h0;
                *(half2*)&outp[(size_t)(row0 + rb + 8) * HH + col] = h1;
            }
        }
    }
}

// ---------------------------------------------------------------------------
// Phase 2: fp16 flash attention, running-max softmax.
// K AND V double-buffered -> ONE __syncthreads per tile, prefetch overlaps
// the whole tile's compute. Conditional O-rescale skip when max unchanged.
// Grid (16, 32), 128 threads. Warp w owns Q rows [16w, 16w+16).
// ---------------------------------------------------------------------------
__global__ __launch_bounds__(128) void attn_kernel(
    const float* __restrict__ mask, float* __restrict__ out)
{
    extern __shared__ char smem[];
    const uint32_t sb = smem_u32(smem);
    __half* Ph = (__half*)(smem + SM_P);

    const int tid = threadIdx.x;
    const int lane = tid & 31, w = tid >> 5, g = lane >> 2, c = lane & 3;
    const int b = blockIdx.y;
    const int i0 = blockIdx.x * 64;
    const int rb = w * 16 + g;
    const int gi = i0 + rb;

    const char* kg = (const char*)(g_k + (size_t)b * NN * HH);
    const char* vg = (const char*)(g_v + (size_t)b * NN * HH);

    const uint32_t kbase = (uint32_t)(((lane & 7) + ((lane >> 4) & 1) * 8) * (KS2 * 2)
                                      + ((lane >> 3) & 1) * 16);
    const uint32_t vbase = (uint32_t)((lane & 15) * (KS2 * 2) + (lane >> 4) * 16);

    // Prologue: prefetch K(0), V(0) into buffer set 0.
    {
        #pragma unroll
        for (int i = 0; i < 4; i++) {
            int idx = tid + i * 128;
            int r = idx >> 4, c16 = idx & 15;
            CP_ASYNC16(sb + SM_K0 + (uint32_t)(r * (KS2 * 2) + c16 * 16), kg + r * 256 + c16 * 16);
            CP_ASYNC16(sb + SM_V0 + (uint32_t)(r * (KS2 * 2) + c16 * 16), vg + r * 256 + c16 * 16);
        }
        CP_COMMIT();
    }

    unsigned qa[8][4];
    {
        const uint32_t* q0 = (const uint32_t*)(g_q + ((size_t)b * NN + gi) * HH);
        const uint32_t* q1 = (const uint32_t*)(g_q + ((size_t)b * NN + gi + 8) * HH);
        #pragma unroll
        for (int ks = 0; ks < 8; ks++) {
            qa[ks][0] = q0[ks * 8 + c];
            qa[ks][1] = q1[ks * 8 + c];
            qa[ks][2] = q0[ks * 8 + c + 4];
            qa[ks][3] = q1[ks * 8 + c + 4];
        }
    }

    float o[16][4];
    #pragma unroll
    for (int n = 0; n < 16; n++) { o[n][0] = o[n][1] = o[n][2] = o[n][3] = 0.f; }
    float l0 = 0.f, l1 = 0.f;
    float m0 = -MNEG, m1 = -MNEG;

    const float2* mr0 = (const float2*)(mask + ((size_t)b * NN + gi) * NN);
    const float2* mr1 = (const float2*)(mask + ((size_t)b * NN + gi + 8) * NN);

    for (int t = 0; t < NTILES; t++) {
        const int j0 = t * KT;

        // Own copies of tile t landed (issued a full tile ago -> near-free)...
        CP_WAIT0();
        // ...and make everyone's copies visible + (t-1) buffers fully consumed.
        __syncthreads();

        // Prefetch tile t+1 into the other buffer set (overlaps ALL of tile t).
        if (t + 1 < NTILES) {
            const uint32_t koff = ((t + 1) & 1) ? SM_K1 : SM_K0;
            const uint32_t voff = ((t + 1) & 1) ? SM_V1 : SM_V0;
            const char* ksrc = kg + (size_t)(t + 1) * KT * HH * 2;
            const char* vsrc = vg + (size_t)(t + 1) * KT * HH * 2;
            #pragma unroll
            for (int i = 0; i < 4; i++) {
                int idx = tid + i * 128;
                int r = idx >> 4, c16 = idx & 15;
                CP_ASYNC16(sb + koff + (uint32_t)(r * (KS2 * 2) + c16 * 16), ksrc + r * 256 + c16 * 16);
                CP_ASYNC16(sb + voff + (uint32_t)(r * (KS2 * 2) + c16 * 16), vsrc + r * 256 + c16 * 16);
            }
        }
        CP_COMMIT();

        const uint32_t ktile = sb + ((t & 1) ? SM_K1 : SM_K0);
        const uint32_t vtile = sb + ((t & 1) ? SM_V1 : SM_V0);

        // --- mask fragments (issue early; hidden under S-MMA) ---
        float2 ma[4], mb[4];
        #pragma unroll
        for (int nb = 0; nb < 4; nb++) {
            int jj = (j0 + nb * 8 + 2 * c) >> 1;
            ma[nb] = mr0[jj];
            mb[nb] = mr1[jj];
        }

        // --- S = Q K^T ---
        float s[4][4];
        #pragma unroll
        for (int nb = 0; nb < 4; nb++) { s[nb][0] = s[nb][1] = s[nb][2] = s[nb][3] = 0.f; }
        #pragma unroll
        for (int nb2 = 0; nb2 < 2; nb2++) {
            #pragma unroll
            for (int ks = 0; ks < 8; ks++) {
                unsigned b0, b1, b2, b3;
                LDSM_X4(b0, b1, b2, b3,
                        ktile + kbase + (uint32_t)(nb2 * 16 * (KS2 * 2) + ks * 32));
                mma_f16(s[nb2 * 2], qa[ks][0], qa[ks][1], qa[ks][2], qa[ks][3], b0, b1);
                mma_f16(s[nb2 * 2 + 1], qa[ks][0], qa[ks][1], qa[ks][2], qa[ks][3], b2, b3);
            }
        }

        // --- running-max softmax: P = mask * exp(s - m_row), P in [0,1] ---
        float mx0 = m0, mx1 = m1;
        #pragma unroll
        for (int nb = 0; nb < 4; nb++) {
            mx0 = fmaxf(mx0, fmaxf(s[nb][0] * ma[nb].x - MNEG * (1.f - ma[nb].x),
                                   s[nb][1] * ma[nb].y - MNEG * (1.f - ma[nb].y)));
            mx1 = fmaxf(mx1, fmaxf(s[nb][2] * mb[nb].x - MNEG * (1.f - mb[nb].x),
                                   s[nb][3] * mb[nb].y - MNEG * (1.f - mb[nb].y)));
        }
        mx0 = fmaxf(mx0, __shfl_xor_sync(0xffffffffu, mx0, 1));
        mx0 = fmaxf(mx0, __shfl_xor_sync(0xffffffffu, mx0, 2));
        mx1 = fmaxf(mx1, __shfl_xor_sync(0xffffffffu, mx1, 1));
        mx1 = fmaxf(mx1, __shfl_xor_sync(0xffffffffu, mx1, 2));

        const float sc0 = __expf(m0 - mx0);
        const float sc1 = __expf(m1 - mx1);
        m0 = mx0; m1 = mx1;

        float rs0 = 0.f, rs1 = 0.f;
        #pragma unroll
        for (int nb = 0; nb < 4; nb++) {
            s[nb][0] = ma[nb].x * __expf(s[nb][0] - mx0);
            s[nb][1] = ma[nb].y * __expf(s[nb][1] - mx0);
            s[nb][2] = mb[nb].x * __expf(s[nb][2] - mx1);
            s[nb][3] = mb[nb].y * __expf(s[nb][3] - mx1);
            rs0 += s[nb][0] + s[nb][1];
            rs1 += s[nb][2] + s[nb][3];
        }
        rs0 += __shfl_xor_sync(0xffffffffu, rs0, 1);
        rs0 += __shfl_xor_sync(0xffffffffu, rs0, 2);
        rs1 += __shfl_xor_sync(0xffffffffu, rs1, 1);
        rs1 += __shfl_xor_sync(0xffffffffu, rs1, 2);
        l0 = l0 * sc0 + rs0;
        l1 = l1 * sc1 + rs1;

        // --- rescale O only when the running max actually moved ---
        const bool norescale =
            __all_sync(0xffffffffu, (sc0 == 1.0f) && (sc1 == 1.0f));
        if (!norescale) {
            #pragma unroll
            for (int n = 0; n < 16; n++) {
                o[n][0] *= sc0; o[n][1] *= sc0; o[n][2] *= sc1; o[n][3] *= sc1;
            }
        }

        // --- stage P (fp16, in [0,1]) to warp-private smem rows ---
        __syncwarp();
        #pragma unroll
        for (int nb = 0; nb < 4; nb++) {
            int col = nb * 8 + 2 * c;
            *(half2*)&Ph[rb * PS2 + col]       = __floats2half2_rn(s[nb][0], s[nb][1]);
            *(half2*)&Ph[(rb + 8) * PS2 + col] = __floats2half2_rn(s[nb][2], s[nb][3]);
        }
        __syncwarp();
        unsigned pa[2][4];
        {
            const uint32_t* p0 = (const uint32_t*)&Ph[rb * PS2];
            const uint32_t* p1 = (const uint32_t*)&Ph[(rb + 8) * PS2];
            #pragma unroll
            for (int ks = 0; ks < 2; ks++) {
                pa[ks][0] = p0[ks * 8 + c];
                pa[ks][1] = p1[ks * 8 + c];
                pa[ks][2] = p0[ks * 8 + c + 4];
                pa[ks][3] = p1[ks * 8 + c + 4];
            }
        }

        // --- O += P V ---
        #pragma unroll
        for (int ks = 0; ks < 2; ks++) {
            #pragma unroll
            for (int nb2 = 0; nb2 < 8; nb2++) {
                unsigned b0, b1, b2, b3;
                LDSM_X4_T(b0, b1, b2, b3,
                          vtile + vbase + (uint32_t)(ks * 16 * (KS2 * 2) + nb2 * 32));
                mma_f16(o[nb2 * 2], pa[ks][0], pa[ks][1], pa[ks][2], pa[ks][3], b0, b1);
                mma_f16(o[nb2 * 2 + 1], pa[ks][0], pa[ks][1], pa[ks][2], pa[ks][3], b2, b3);
            }
        }
    }

    const float inv0 = 1.0f / l0, inv1 = 1.0f / l1;
    float* op = out + ((size_t)b * NN + gi) * HH;
    #pragma unroll
    for (int n = 0; n < 16; n++) {
        int col = n * 8 + 2 * c;
        float2 r0 = make_float2(o[n][0] * inv0, o[n][1] * inv0);
        float2 r1 = make_float2(o[n][2] * inv1, o[n][3] * inv1);
        *(float2*)&op[col] = r0;
        *(float2*)&op[8 * HH + col] = r1;
    }
}

extern "C" void kernel_launch(void* const* d_in, const int* in_sizes, int n_in,
                              void* d_out, int out_size) {
    const float* x    = (const float*)d_in[0];
    const float* mask = (const float*)d_in[1];
    const float* Wv   = (const float*)d_in[2];
    const float* bv   = (const float*)d_in[3];
    const float* Wk   = (const float*)d_in[4];
    const float* bk   = (const float*)d_in[5];
    const float* Wq   = (const float*)d_in[6];
    const float* bq   = (const float*)d_in[7];
    float* out = (float*)d_out;
    (void)in_sizes; (void)n_in; (void)out_size;

    cudaFuncSetAttribute(proj_kernel, cudaFuncAttributeMaxDynamicSharedMemorySize, PSM_TOTAL);
    proj_kernel<<<(BB * NN) / 64, 128, PSM_TOTAL>>>(x, Wv, bv, Wk, bk, Wq, bq);

    cudaFuncSetAttribute(attn_kernel, cudaFuncAttributeMaxDynamicSharedMemorySize, SM_TOTAL);
    attn_kernel<<<dim3(NN / 64, BB), 128, SM_TOTAL>>>(mask, out);
}

// round 13
// speedup vs baseline: 1.1188x; 1.1188x over previous
#include <cuda_runtime.h>
#include <cuda_fp16.h>
#include <math.h>
#include <stdint.h>

#define BB 32
#define NN 1024
#define DD 128
#define HH 128
#define MNEG 100.0f

#define KT 32
#define NTILES (NN / KT)

// ---- proj smem layout (bytes) ----
#define PX_STRIDE 132
#define PW_STRIDE 136
#define PSM_X  0
#define PSM_W0 33792
#define PSM_W1 68608
#define PSM_TOTAL 103424

// ---- attn smem layout (bytes). K/V rows: 136 halfs = 272B (conflict-free) ----
#define KS2 136
#define PS2 40
#define SM_K   0                       // 32 x 272B = 8704
#define SM_V0  8704                    // 8704
#define SM_V1  17408                   // 8704
#define SM_P   26112                   // 64 x 80B = 5120
#define SM_TOTAL 31360

// Projected q/k/v in fp16 (natural [B][N][H] layout).
__device__ __align__(16) __half g_q[BB * NN * HH];
__device__ __align__(16) __half g_k[BB * NN * HH];
__device__ __align__(16) __half g_v[BB * NN * HH];

__device__ __forceinline__ unsigned tf32u(float x) {
    unsigned u;
    asm("cvt.rna.tf32.f32 %0, %1;" : "=r"(u) : "f"(x));
    return u;
}

__device__ __forceinline__ uint32_t smem_u32(const void* p) {
    uint32_t a;
    asm("{ .reg .u64 t; cvta.to.shared.u64 t, %1; cvt.u32.u64 %0, t; }" : "=r"(a) : "l"(p));
    return a;
}

#define CP_ASYNC16(dst_u32, src_ptr) \
    asm volatile("cp.async.cg.shared.global [%0], [%1], 16;" \
                 :: "r"(dst_u32), "l"(src_ptr) : "memory")
#define CP_COMMIT() asm volatile("cp.async.commit_group;" ::: "memory")
#define CP_WAIT0()  asm volatile("cp.async.wait_group 0;" ::: "memory")
#define CP_WAIT1()  asm volatile("cp.async.wait_group 1;" ::: "memory")

#define LDSM_X4(r0, r1, r2, r3, addr) \
    asm volatile("ldmatrix.sync.aligned.m8n8.x4.shared.b16 {%0,%1,%2,%3}, [%4];" \
                 : "=r"(r0), "=r"(r1), "=r"(r2), "=r"(r3) : "r"(addr))
#define LDSM_X4_T(r0, r1, r2, r3, addr) \
    asm volatile("ldmatrix.sync.aligned.m8n8.x4.trans.shared.b16 {%0,%1,%2,%3}, [%4];" \
                 : "=r"(r0), "=r"(r1), "=r"(r2), "=r"(r3) : "r"(addr))

__device__ __forceinline__ void mma_f16(float* cc,
                                        unsigned a0, unsigned a1, unsigned a2, unsigned a3,
                                        unsigned b0, unsigned b1) {
    asm volatile(
        "mma.sync.aligned.m16n8k16.row.col.f32.f16.f16.f32 "
        "{%0,%1,%2,%3}, {%4,%5,%6,%7}, {%8,%9}, {%0,%1,%2,%3};\n"
        : "+f"(cc[0]), "+f"(cc[1]), "+f"(cc[2]), "+f"(cc[3])
        : "r"(a0), "r"(a1), "r"(a2), "r"(a3), "r"(b0), "r"(b1));
}

__device__ __forceinline__ void mma_tf32(float* cc,
                                         unsigned a0, unsigned a1, unsigned a2, unsigned a3,
                                         unsigned b0, unsigned b1) {
    asm volatile(
        "mma.sync.aligned.m16n8k8.row.col.f32.tf32.tf32.f32 "
        "{%0,%1,%2,%3}, {%4,%5,%6,%7}, {%8,%9}, {%0,%1,%2,%3};\n"
        : "+f"(cc[0]), "+f"(cc[1]), "+f"(cc[2]), "+f"(cc[3])
        : "r"(a0), "r"(a1), "r"(a2), "r"(a3), "r"(b0), "r"(b1));
}

// ---------------------------------------------------------------------------
// Phase 1: q/k/v = relu(x @ W + b) in tf32 MMA, stored as fp16. (unchanged)
// ---------------------------------------------------------------------------
__global__ __launch_bounds__(128, 3) void proj_kernel(
    const float* __restrict__ x,
    const float* __restrict__ Wv, const float* __restrict__ bv,
    const float* __restrict__ Wk, const float* __restrict__ bk,
    const float* __restrict__ Wq, const float* __restrict__ bq)
{
    extern __shared__ char smem[];
    const uint32_t sb = smem_u32(smem);
    float* Xs = (float*)(smem + PSM_X);
    __shared__ float bs3[3][HH];

    const int tid = threadIdx.x;
    const int lane = tid & 31, w = tid >> 5, g = lane >> 2, c = lane & 3;
    const int row0 = blockIdx.x * 64;

    const float* const wp3[3] = {Wv, Wk, Wq};
    __half* const op3[3] = {g_v, g_k, g_q};

    {
        const char* xg = (const char*)(x + (size_t)row0 * DD);
        const char* wsrc = (const char*)Wv;
        #pragma unroll
        for (int i = 0; i < 16; i++) {
            int idx = tid + i * 128;
            int r = idx >> 5, c16 = idx & 31;
            CP_ASYNC16(sb + PSM_X + (uint32_t)(r * (PX_STRIDE * 4) + c16 * 16), xg + idx * 16);
            CP_ASYNC16(sb + PSM_W0 + (uint32_t)(r * (PW_STRIDE * 4) + c16 * 16), wsrc + idx * 16);
        }
        CP_COMMIT();
    }
    {
        const char* wsrc = (const char*)(Wv + 64 * HH);
        #pragma unroll
        for (int i = 0; i < 16; i++) {
            int idx = tid + i * 128;
            int r = idx >> 5, c16 = idx & 31;
            CP_ASYNC16(sb + PSM_W1 + (uint32_t)(r * (PW_STRIDE * 4) + c16 * 16), wsrc + idx * 16);
        }
        CP_COMMIT();
    }

    if (tid < HH) {
        bs3[0][tid] = bv[tid];
        bs3[1][tid] = bk[tid];
        bs3[2][tid] = bq[tid];
    }

    const int rb = w * 16 + g;
    unsigned xa[16][4];
    float acc[16][4];

    for (int p = 0; p < 6; p++) {
        const int wi = p >> 1, h = p & 1;
        if (p >= 4) CP_WAIT0(); else CP_WAIT1();
        __syncthreads();

        if (p == 0) {
            #pragma unroll
            for (int kk = 0; kk < 16; kk++) {
                xa[kk][0] = tf32u(Xs[rb * PX_STRIDE + kk * 8 + c]);
                xa[kk][1] = tf32u(Xs[(rb + 8) * PX_STRIDE + kk * 8 + c]);
                xa[kk][2] = tf32u(Xs[rb * PX_STRIDE + kk * 8 + c + 4]);
                xa[kk][3] = tf32u(Xs[(rb + 8) * PX_STRIDE + kk * 8 + c + 4]);
            }
        }
        if (h == 0) {
            #pragma unroll
            for (int nb = 0; nb < 16; nb++)
                acc[nb][0] = acc[nb][1] = acc[nb][2] = acc[nb][3] = 0.f;
        }

        const float* Wb = (const float*)(smem + ((p & 1) ? PSM_W1 : PSM_W0));
        #pragma unroll
        for (int nb = 0; nb < 16; nb++) {
            #pragma unroll
            for (int k2 = 0; k2 < 8; k2++) {
                int kk = h * 8 + k2;
                unsigned b0 = tf32u(Wb[(k2 * 8 + c) * PW_STRIDE + nb * 8 + g]);
                unsigned b1 = tf32u(Wb[(k2 * 8 + c + 4) * PW_STRIDE + nb * 8 + g]);
                mma_tf32(acc[nb], xa[kk][0], xa[kk][1], xa[kk][2], xa[kk][3], b0, b1);
            }
        }
        __syncthreads();

        if (p + 2 < 6) {
            const int pw = p + 2;
            const char* wsrc = (const char*)(wp3[pw >> 1] + (pw & 1) * 64 * HH);
            const uint32_t dst = sb + ((p & 1) ? PSM_W1 : PSM_W0);
            #pragma unroll
            for (int i = 0; i < 16; i++) {
                int idx = tid + i * 128;
                int r = idx >> 5, c16 = idx & 31;
                CP_ASYNC16(dst + (uint32_t)(r * (PW_STRIDE * 4) + c16 * 16), wsrc + idx * 16);
            }
            CP_COMMIT();
        }

        if (h == 1) {
            __half* outp = op3[wi];
            #pragma unroll
            for (int nb = 0; nb < 16; nb++) {
                int col = nb * 8 + 2 * c;
                float bb0 = bs3[wi][col], bb1 = bs3[wi][col + 1];
                half2 h0 = __floats2half2_rn(fmaxf(acc[nb][0] + bb0, 0.f),
                                             fmaxf(acc[nb][1] + bb1, 0.f));
                half2 h1 = __floats2half2_rn(fmaxf(acc[nb][2] + bb0, 0.f),
                                             fmaxf(acc[nb][3] + bb1, 0.f));
                *(half2*)&outp[(size_t)(row0 + rb) * HH + col] = h0;
                *(half2*)&outp[(size_t)(row0 + rb + 8) * HH + col] = h1;
            }
        }
    }
}

// ---------------------------------------------------------------------------
// Phase 2: fp16 flash attention, R11 pipeline (K single-buf, V double-buf,
// two offset syncs per tile) + raw-max softmax + conditional rescale skip.
// Grid (16, 32), 128 threads. Warp w owns Q rows [16w, 16w+16).
// ---------------------------------------------------------------------------
__global__ __launch_bounds__(128) void attn_kernel(
    const float* __restrict__ mask, float* __restrict__ out)
{
    extern __shared__ char smem[];
    const uint32_t sb = smem_u32(smem);
    __half* Ph = (__half*)(smem + SM_P);

    const int tid = threadIdx.x;
    const int lane = tid & 31, w = tid >> 5, g = lane >> 2, c = lane & 3;
    const int b = blockIdx.y;
    const int i0 = blockIdx.x * 64;
    const int rb = w * 16 + g;
    const int gi = i0 + rb;

    const char* kg = (const char*)(g_k + (size_t)b * NN * HH);
    const char* vg = (const char*)(g_v + (size_t)b * NN * HH);

    const uint32_t kbase = (uint32_t)(((lane & 7) + ((lane >> 4) & 1) * 8) * (KS2 * 2)
                                      + ((lane >> 3) & 1) * 16);
    const uint32_t vbase = (uint32_t)((lane & 15) * (KS2 * 2) + (lane >> 4) * 16);

    // Prologue: K(0), V(0)
    {
        #pragma unroll
        for (int i = 0; i < 4; i++) {
            int idx = tid + i * 128;
            int r = idx >> 4, c16 = idx & 15;
            CP_ASYNC16(sb + SM_K  + (uint32_t)(r * (KS2 * 2) + c16 * 16), kg + r * 256 + c16 * 16);
            CP_ASYNC16(sb + SM_V0 + (uint32_t)(r * (KS2 * 2) + c16 * 16), vg + r * 256 + c16 * 16);
        }
        CP_COMMIT();
    }

    unsigned qa[8][4];
    {
        const uint32_t* q0 = (const uint32_t*)(g_q + ((size_t)b * NN + gi) * HH);
        const uint32_t* q1 = (const uint32_t*)(g_q + ((size_t)b * NN + gi + 8) * HH);
        #pragma unroll
        for (int ks = 0; ks < 8; ks++) {
            qa[ks][0] = q0[ks * 8 + c];
            qa[ks][1] = q1[ks * 8 + c];
            qa[ks][2] = q0[ks * 8 + c + 4];
            qa[ks][3] = q1[ks * 8 + c + 4];
        }
    }

    float o[16][4];
    #pragma unroll
    for (int n = 0; n < 16; n++) { o[n][0] = o[n][1] = o[n][2] = o[n][3] = 0.f; }
    float l0 = 0.f, l1 = 0.f;
    float m0 = -MNEG, m1 = -MNEG;

    const float2* mr0 = (const float2*)(mask + ((size_t)b * NN + gi) * NN);
    const float2* mr1 = (const float2*)(mask + ((size_t)b * NN + gi + 8) * NN);

    CP_WAIT0();
    __syncthreads();

    for (int t = 0; t < NTILES; t++) {
        const int j0 = t * KT;
        const int tn = (t + 1) & (NTILES - 1);

        // --- prefetch V(t+1) ---
        {
            const uint32_t vdst = sb + (((t + 1) & 1) ? SM_V1 : SM_V0);
            const char* vsrc = vg + (size_t)tn * KT * HH * 2;
            #pragma unroll
            for (int i = 0; i < 4; i++) {
                int idx = tid + i * 128;
                int r = idx >> 4, c16 = idx & 15;
                CP_ASYNC16(vdst + (uint32_t)(r * (KS2 * 2) + c16 * 16), vsrc + r * 256 + c16 * 16);
            }
            CP_COMMIT();
        }

        // --- mask fragments ---
        float2 ma[4], mb[4];
        #pragma unroll
        for (int nb = 0; nb < 4; nb++) {
            int jj = (j0 + nb * 8 + 2 * c) >> 1;
            ma[nb] = mr0[jj];
            mb[nb] = mr1[jj];
        }

        // --- S = Q K^T ---
        float s[4][4];
        #pragma unroll
        for (int nb = 0; nb < 4; nb++) { s[nb][0] = s[nb][1] = s[nb][2] = s[nb][3] = 0.f; }
        #pragma unroll
        for (int nb2 = 0; nb2 < 2; nb2++) {
            #pragma unroll
            for (int ks = 0; ks < 8; ks++) {
                unsigned b0, b1, b2, b3;
                LDSM_X4(b0, b1, b2, b3,
                        sb + SM_K + kbase + (uint32_t)(nb2 * 16 * (KS2 * 2) + ks * 32));
                mma_f16(s[nb2 * 2], qa[ks][0], qa[ks][1], qa[ks][2], qa[ks][3], b0, b1);
                mma_f16(s[nb2 * 2 + 1], qa[ks][0], qa[ks][1], qa[ks][2], qa[ks][3], b2, b3);
            }
        }

        __syncthreads();   // all warps done reading K(t)

        // --- prefetch K(t+1) ---
        {
            const char* ksrc = kg + (size_t)tn * KT * HH * 2;
            #pragma unroll
            for (int i = 0; i < 4; i++) {
                int idx = tid + i * 128;
                int r = idx >> 4, c16 = idx & 15;
                CP_ASYNC16(sb + SM_K + (uint32_t)(r * (KS2 * 2) + c16 * 16), ksrc + r * 256 + c16 * 16);
            }
            CP_COMMIT();
        }

        // --- raw-max softmax: any m >= row-max is valid (cancels in P V / l).
        //     Masked entries are killed by the mask MULTIPLIER, not the max. ---
        float mx0 = m0, mx1 = m1;
        #pragma unroll
        for (int nb = 0; nb < 4; nb++) {
            mx0 = fmaxf(mx0, fmaxf(s[nb][0], s[nb][1]));
            mx1 = fmaxf(mx1, fmaxf(s[nb][2], s[nb][3]));
        }
        mx0 = fmaxf(mx0, __shfl_xor_sync(0xffffffffu, mx0, 1));
        mx0 = fmaxf(mx0, __shfl_xor_sync(0xffffffffu, mx0, 2));
        mx1 = fmaxf(mx1, __shfl_xor_sync(0xffffffffu, mx1, 1));
        mx1 = fmaxf(mx1, __shfl_xor_sync(0xffffffffu, mx1, 2));

        const float sc0 = __expf(m0 - mx0);
        const float sc1 = __expf(m1 - mx1);
        m0 = mx0; m1 = mx1;

        float rs0 = 0.f, rs1 = 0.f;
        #pragma unroll
        for (int nb = 0; nb < 4; nb++) {
            s[nb][0] = ma[nb].x * __expf(s[nb][0] - mx0);
            s[nb][1] = ma[nb].y * __expf(s[nb][1] - mx0);
            s[nb][2] = mb[nb].x * __expf(s[nb][2] - mx1);
            s[nb][3] = mb[nb].y * __expf(s[nb][3] - mx1);
            rs0 += s[nb][0] + s[nb][1];
            rs1 += s[nb][2] + s[nb][3];
        }
        rs0 += __shfl_xor_sync(0xffffffffu, rs0, 1);
        rs0 += __shfl_xor_sync(0xffffffffu, rs0, 2);
        rs1 += __shfl_xor_sync(0xffffffffu, rs1, 1);
        rs1 += __shfl_xor_sync(0xffffffffu, rs1, 2);
        l0 = l0 * sc0 + rs0;
        l1 = l1 * sc1 + rs1;

        // --- rescale O only when the running max actually moved (raw max is
        //     monotone over a fixed population -> stabilizes quickly) ---
        const bool norescale =
            __all_sync(0xffffffffu, (sc0 == 1.0f) && (sc1 == 1.0f));
        if (!norescale) {
            #pragma unroll
            for (int n = 0; n < 16; n++) {
                o[n][0] *= sc0; o[n][1] *= sc0; o[n][2] *= sc1; o[n][3] *= sc1;
            }
        }

        // --- stage P (fp16, in [0,1]) to warp-private smem rows ---
        __syncwarp();
        #pragma unroll
        for (int nb = 0; nb < 4; nb++) {
            int col = nb * 8 + 2 * c;
            *(half2*)&Ph[rb * PS2 + col]       = __floats2half2_rn(s[nb][0], s[nb][1]);
            *(half2*)&Ph[(rb + 8) * PS2 + col] = __floats2half2_rn(s[nb][2], s[nb][3]);
        }
        __syncwarp();
        unsigned pa[2][4];
        {
            const uint32_t* p0 = (const uint32_t*)&Ph[rb * PS2];
            const uint32_t* p1 = (const uint32_t*)&Ph[(rb + 8) * PS2];
            #pragma unroll
            for (int ks = 0; ks < 2; ks++) {
                pa[ks][0] = p0[ks * 8 + c];
                pa[ks][1] = p1[ks * 8 + c];
                pa[ks][2] = p0[ks * 8 + c + 4];
                pa[ks][3] = p1[ks * 8 + c + 4];
            }
        }

        // --- O += P V ---
        const uint32_t vtile = sb + ((t & 1) ? SM_V1 : SM_V0);
        #pragma unroll
        for (int ks = 0; ks < 2; ks++) {
            #pragma unroll
            for (int nb2 = 0; nb2 < 8; nb2++) {
                unsigned b0, b1, b2, b3;
                LDSM_X4_T(b0, b1, b2, b3,
                          vtile + vbase + (uint32_t)(ks * 16 * (KS2 * 2) + nb2 * 32));
                mma_f16(o[nb2 * 2], pa[ks][0], pa[ks][1], pa[ks][2], pa[ks][3], b0, b1);
                mma_f16(o[nb2 * 2 + 1], pa[ks][0], pa[ks][1], pa[ks][2], pa[ks][3], b2, b3);
            }
        }

        CP_WAIT0();
        __syncthreads();
    }

    const float inv0 = 1.0f / l0, inv1 = 1.0f / l1;
    float* op = out + ((size_t)b * NN + gi) * HH;
    #pragma unroll
    for (int n = 0; n < 16; n++) {
        int col = n * 8 + 2 * c;
        float2 r0 = make_float2(o[n][0] * inv0, o[n][1] * inv0);
        float2 r1 = make_float2(o[n][2] * inv1, o[n][3] * inv1);
        *(float2*)&op[col] = r0;
        *(float2*)&op[8 * HH + col] = r1;
    }
}

extern "C" void kernel_launch(void* const* d_in, const int* in_sizes, int n_in,
                              void* d_out, int out_size) {
    const float* x    = (const float*)d_in[0];
    const float* mask = (const float*)d_in[1];
    const float* Wv   = (const float*)d_in[2];
    const float* bv   = (const float*)d_in[3];
    const float* Wk   = (const float*)d_in[4];
    const float* bk   = (const float*)d_in[5];
    const float* Wq   = (const float*)d_in[6];
    const float* bq   = (const float*)d_in[7];
    float* out = (float*)d_out;
    (void)in_sizes; (void)n_in; (void)out_size;

    cudaFuncSetAttribute(proj_kernel, cudaFuncAttributeMaxDynamicSharedMemorySize, PSM_TOTAL);
    proj_kernel<<<(BB * NN) / 64, 128, PSM_TOTAL>>>(x, Wv, bv, Wk, bk, Wq, bq);

    cudaFuncSetAttribute(attn_kernel, cudaFuncAttributeMaxDynamicSharedMemorySize, SM_TOTAL);
    attn_kernel<<<dim3(NN / 64, BB), 128, SM_TOTAL>>>(mask, out);
}

// round 16
// speedup vs baseline: 1.1969x; 1.0698x over previous
#include <cuda_runtime.h>
#include <cuda_fp16.h>
#include <math.h>
#include <stdint.h>

#define BB 32
#define NN 1024
#define DD 128
#define HH 128
#define MNEG 100.0f

#define KT 32
#define NTILES (NN / KT)

// ---- proj smem layout (bytes) ----
#define PX_STRIDE 132
#define PW_STRIDE 136
#define PSM_X  0
#define PSM_W0 33792
#define PSM_W1 68608
#define PSM_TOTAL 103424

// ---- attn smem layout (bytes). K/V rows: 136 halfs = 272B (conflict-free) ----
#define KS2 136
#define PS2 40
#define SM_K   0                       // 32 x 272B = 8704
#define SM_V0  8704                    // 8704
#define SM_V1  17408                   // 8704
#define SM_P   26112                   // 64 x 80B = 5120
#define SM_TOTAL 31360

// Projected q/k/v in fp16 (natural [B][N][H] layout).
__device__ __align__(16) __half g_q[BB * NN * HH];
__device__ __align__(16) __half g_k[BB * NN * HH];
__device__ __align__(16) __half g_v[BB * NN * HH];

__device__ __forceinline__ unsigned tf32u(float x) {
    unsigned u;
    asm("cvt.rna.tf32.f32 %0, %1;" : "=r"(u) : "f"(x));
    return u;
}

__device__ __forceinline__ uint32_t smem_u32(const void* p) {
    uint32_t a;
    asm("{ .reg .u64 t; cvta.to.shared.u64 t, %1; cvt.u32.u64 %0, t; }" : "=r"(a) : "l"(p));
    return a;
}

#define CP_ASYNC16(dst_u32, src_ptr) \
    asm volatile("cp.async.cg.shared.global [%0], [%1], 16;" \
                 :: "r"(dst_u32), "l"(src_ptr) : "memory")
#define CP_COMMIT() asm volatile("cp.async.commit_group;" ::: "memory")
#define CP_WAIT0()  asm volatile("cp.async.wait_group 0;" ::: "memory")
#define CP_WAIT1()  asm volatile("cp.async.wait_group 1;" ::: "memory")

#define LDSM_X4(r0, r1, r2, r3, addr) \
    asm volatile("ldmatrix.sync.aligned.m8n8.x4.shared.b16 {%0,%1,%2,%3}, [%4];" \
                 : "=r"(r0), "=r"(r1), "=r"(r2), "=r"(r3) : "r"(addr))
#define LDSM_X4_T(r0, r1, r2, r3, addr) \
    asm volatile("ldmatrix.sync.aligned.m8n8.x4.trans.shared.b16 {%0,%1,%2,%3}, [%4];" \
                 : "=r"(r0), "=r"(r1), "=r"(r2), "=r"(r3) : "r"(addr))

__device__ __forceinline__ void mma_f16(float* cc,
                                        unsigned a0, unsigned a1, unsigned a2, unsigned a3,
                                        unsigned b0, unsigned b1) {
    asm volatile(
        "mma.sync.aligned.m16n8k16.row.col.f32.f16.f16.f32 "
        "{%0,%1,%2,%3}, {%4,%5,%6,%7}, {%8,%9}, {%0,%1,%2,%3};\n"
        : "+f"(cc[0]), "+f"(cc[1]), "+f"(cc[2]), "+f"(cc[3])
        : "r"(a0), "r"(a1), "r"(a2), "r"(a3), "r"(b0), "r"(b1));
}

__device__ __forceinline__ void mma_tf32(float* cc,
                                         unsigned a0, unsigned a1, unsigned a2, unsigned a3,
                                         unsigned b0, unsigned b1) {
    asm volatile(
        "mma.sync.aligned.m16n8k8.row.col.f32.tf32.tf32.f32 "
        "{%0,%1,%2,%3}, {%4,%5,%6,%7}, {%8,%9}, {%0,%1,%2,%3};\n"
        : "+f"(cc[0]), "+f"(cc[1]), "+f"(cc[2]), "+f"(cc[3])
        : "r"(a0), "r"(a1), "r"(a2), "r"(a3), "r"(b0), "r"(b1));
}

// ---------------------------------------------------------------------------
// Phase 1: q/k/v = relu(x @ W + b) in tf32 MMA, stored as fp16. (unchanged)
// ---------------------------------------------------------------------------
__global__ __launch_bounds__(128, 3) void proj_kernel(
    const float* __restrict__ x,
    const float* __restrict__ Wv, const float* __restrict__ bv,
    const float* __restrict__ Wk, const float* __restrict__ bk,
    const float* __restrict__ Wq, const float* __restrict__ bq)
{
    extern __shared__ char smem[];
    const uint32_t sb = smem_u32(smem);
    float* Xs = (float*)(smem + PSM_X);
    __shared__ float bs3[3][HH];

    const int tid = threadIdx.x;
    const int lane = tid & 31, w = tid >> 5, g = lane >> 2, c = lane & 3;
    const int row0 = blockIdx.x * 64;

    const float* const wp3[3] = {Wv, Wk, Wq};
    __half* const op3[3] = {g_v, g_k, g_q};

    {
        const char* xg = (const char*)(x + (size_t)row0 * DD);
        const char* wsrc = (const char*)Wv;
        #pragma unroll
        for (int i = 0; i < 16; i++) {
            int idx = tid + i * 128;
            int r = idx >> 5, c16 = idx & 31;
            CP_ASYNC16(sb + PSM_X + (uint32_t)(r * (PX_STRIDE * 4) + c16 * 16), xg + idx * 16);
            CP_ASYNC16(sb + PSM_W0 + (uint32_t)(r * (PW_STRIDE * 4) + c16 * 16), wsrc + idx * 16);
        }
        CP_COMMIT();
    }
    {
        const char* wsrc = (const char*)(Wv + 64 * HH);
        #pragma unroll
        for (int i = 0; i < 16; i++) {
            int idx = tid + i * 128;
            int r = idx >> 5, c16 = idx & 31;
            CP_ASYNC16(sb + PSM_W1 + (uint32_t)(r * (PW_STRIDE * 4) + c16 * 16), wsrc + idx * 16);
        }
        CP_COMMIT();
    }

    if (tid < HH) {
        bs3[0][tid] = bv[tid];
        bs3[1][tid] = bk[tid];
        bs3[2][tid] = bq[tid];
    }

    const int rb = w * 16 + g;
    unsigned xa[16][4];
    float acc[16][4];

    for (int p = 0; p < 6; p++) {
        const int wi = p >> 1, h = p & 1;
        if (p >= 4) CP_WAIT0(); else CP_WAIT1();
        __syncthreads();

        if (p == 0) {
            #pragma unroll
            for (int kk = 0; kk < 16; kk++) {
                xa[kk][0] = tf32u(Xs[rb * PX_STRIDE + kk * 8 + c]);
                xa[kk][1] = tf32u(Xs[(rb + 8) * PX_STRIDE + kk * 8 + c]);
                xa[kk][2] = tf32u(Xs[rb * PX_STRIDE + kk * 8 + c + 4]);
                xa[kk][3] = tf32u(Xs[(rb + 8) * PX_STRIDE + kk * 8 + c + 4]);
            }
        }
        if (h == 0) {
            #pragma unroll
            for (int nb = 0; nb < 16; nb++)
                acc[nb][0] = acc[nb][1] = acc[nb][2] = acc[nb][3] = 0.f;
        }

        const float* Wb = (const float*)(smem + ((p & 1) ? PSM_W1 : PSM_W0));
        #pragma unroll
        for (int nb = 0; nb < 16; nb++) {
            #pragma unroll
            for (int k2 = 0; k2 < 8; k2++) {
                int kk = h * 8 + k2;
                unsigned b0 = tf32u(Wb[(k2 * 8 + c) * PW_STRIDE + nb * 8 + g]);
                unsigned b1 = tf32u(Wb[(k2 * 8 + c + 4) * PW_STRIDE + nb * 8 + g]);
                mma_tf32(acc[nb], xa[kk][0], xa[kk][1], xa[kk][2], xa[kk][3], b0, b1);
            }
        }
        __syncthreads();

        if (p + 2 < 6) {
            const int pw = p + 2;
            const char* wsrc = (const char*)(wp3[pw >> 1] + (pw & 1) * 64 * HH);
            const uint32_t dst = sb + ((p & 1) ? PSM_W1 : PSM_W0);
            #pragma unroll
            for (int i = 0; i < 16; i++) {
                int idx = tid + i * 128;
                int r = idx >> 5, c16 = idx & 31;
                CP_ASYNC16(dst + (uint32_t)(r * (PW_STRIDE * 4) + c16 * 16), wsrc + idx * 16);
            }
            CP_COMMIT();
        }

        if (h == 1) {
            __half* outp = op3[wi];
            #pragma unroll
            for (int nb = 0; nb < 16; nb++) {
                int col = nb * 8 + 2 * c;
                float bb0 = bs3[wi][col], bb1 = bs3[wi][col + 1];
                half2 h0 = __floats2half2_rn(fmaxf(acc[nb][0] + bb0, 0.f),
                                             fmaxf(acc[nb][1] + bb1, 0.f));
                half2 h1 = __floats2half2_rn(fmaxf(acc[nb][2] + bb0, 0.f),
                                             fmaxf(acc[nb][3] + bb1, 0.f));
                *(half2*)&outp[(size_t)(row0 + rb) * HH + col] = h0;
                *(half2*)&outp[(size_t)(row0 + rb + 8) * HH + col] = h1;
            }
        }
    }
}

// ---------------------------------------------------------------------------
// Phase 2: fp16 flash attention — EXACT R11 pipeline (K single-buf, V
// double-buf, two offset syncs per tile) + raw-max softmax, UNCONDITIONAL
// rescale (no branch in the tile loop).
// Grid (16, 32), 128 threads. Warp w owns Q rows [16w, 16w+16).
// ---------------------------------------------------------------------------
__global__ __launch_bounds__(128) void attn_kernel(
    const float* __restrict__ mask, float* __restrict__ out)
{
    extern __shared__ char smem[];
    const uint32_t sb = smem_u32(smem);
    __half* Ph = (__half*)(smem + SM_P);

    const int tid = threadIdx.x;
    const int lane = tid & 31, w = tid >> 5, g = lane >> 2, c = lane & 3;
    const int b = blockIdx.y;
    const int i0 = blockIdx.x * 64;
    const int rb = w * 16 + g;
    const int gi = i0 + rb;

    const char* kg = (const char*)(g_k + (size_t)b * NN * HH);
    const char* vg = (const char*)(g_v + (size_t)b * NN * HH);

    const uint32_t kbase = (uint32_t)(((lane & 7) + ((lane >> 4) & 1) * 8) * (KS2 * 2)
                                      + ((lane >> 3) & 1) * 16);
    const uint32_t vbase = (uint32_t)((lane & 15) * (KS2 * 2) + (lane >> 4) * 16);

    // Prologue: K(0), V(0)
    {
        #pragma unroll
        for (int i = 0; i < 4; i++) {
            int idx = tid + i * 128;
            int r = idx >> 4, c16 = idx & 15;
            CP_ASYNC16(sb + SM_K  + (uint32_t)(r * (KS2 * 2) + c16 * 16), kg + r * 256 + c16 * 16);
            CP_ASYNC16(sb + SM_V0 + (uint32_t)(r * (KS2 * 2) + c16 * 16), vg + r * 256 + c16 * 16);
        }
        CP_COMMIT();
    }

    unsigned qa[8][4];
    {
        const uint32_t* q0 = (const uint32_t*)(g_q + ((size_t)b * NN + gi) * HH);
        const uint32_t* q1 = (const uint32_t*)(g_q + ((size_t)b * NN + gi + 8) * HH);
        #pragma unroll
        for (int ks = 0; ks < 8; ks++) {
            qa[ks][0] = q0[ks * 8 + c];
            qa[ks][1] = q1[ks * 8 + c];
            qa[ks][2] = q0[ks * 8 + c + 4];
            qa[ks][3] = q1[ks * 8 + c + 4];
        }
    }

    float o[16][4];
    #pragma unroll
    for (int n = 0; n < 16; n++) { o[n][0] = o[n][1] = o[n][2] = o[n][3] = 0.f; }
    float l0 = 0.f, l1 = 0.f;
    float m0 = -MNEG, m1 = -MNEG;

    const float2* mr0 = (const float2*)(mask + ((size_t)b * NN + gi) * NN);
    const float2* mr1 = (const float2*)(mask + ((size_t)b * NN + gi + 8) * NN);

    CP_WAIT0();
    __syncthreads();

    for (int t = 0; t < NTILES; t++) {
        const int j0 = t * KT;
        const int tn = (t + 1) & (NTILES - 1);

        // --- prefetch V(t+1) ---
        {
            const uint32_t vdst = sb + (((t + 1) & 1) ? SM_V1 : SM_V0);
            const char* vsrc = vg + (size_t)tn * KT * HH * 2;
            #pragma unroll
            for (int i = 0; i < 4; i++) {
                int idx = tid + i * 128;
                int r = idx >> 4, c16 = idx & 15;
                CP_ASYNC16(vdst + (uint32_t)(r * (KS2 * 2) + c16 * 16), vsrc + r * 256 + c16 * 16);
            }
            CP_COMMIT();
        }

        // --- mask fragments ---
        float2 ma[4], mb[4];
        #pragma unroll
        for (int nb = 0; nb < 4; nb++) {
            int jj = (j0 + nb * 8 + 2 * c) >> 1;
            ma[nb] = mr0[jj];
            mb[nb] = mr1[jj];
        }

        // --- S = Q K^T ---
        float s[4][4];
        #pragma unroll
        for (int nb = 0; nb < 4; nb++) { s[nb][0] = s[nb][1] = s[nb][2] = s[nb][3] = 0.f; }
        #pragma unroll
        for (int nb2 = 0; nb2 < 2; nb2++) {
            #pragma unroll
            for (int ks = 0; ks < 8; ks++) {
                unsigned b0, b1, b2, b3;
                LDSM_X4(b0, b1, b2, b3,
                        sb + SM_K + kbase + (uint32_t)(nb2 * 16 * (KS2 * 2) + ks * 32));
                mma_f16(s[nb2 * 2], qa[ks][0], qa[ks][1], qa[ks][2], qa[ks][3], b0, b1);
                mma_f16(s[nb2 * 2 + 1], qa[ks][0], qa[ks][1], qa[ks][2], qa[ks][3], b2, b3);
            }
        }

        __syncthreads();   // all warps done reading K(t)

        // --- prefetch K(t+1) ---
        {
            const char* ksrc = kg + (size_t)tn * KT * HH * 2;
            #pragma unroll
            for (int i = 0; i < 4; i++) {
                int idx = tid + i * 128;
                int r = idx >> 4, c16 = idx & 15;
                CP_ASYNC16(sb + SM_K + (uint32_t)(r * (KS2 * 2) + c16 * 16), ksrc + r * 256 + c16 * 16);
            }
            CP_COMMIT();
        }

        // --- raw-max softmax: any m >= row-max of kept entries is valid
        //     (cancels in P V / l). Mask kills entries via the multiplier. ---
        float mx0 = m0, mx1 = m1;
        #pragma unroll
        for (int nb = 0; nb < 4; nb++) {
            mx0 = fmaxf(mx0, fmaxf(s[nb][0], s[nb][1]));
            mx1 = fmaxf(mx1, fmaxf(s[nb][2], s[nb][3]));
        }
        mx0 = fmaxf(mx0, __shfl_xor_sync(0xffffffffu, mx0, 1));
        mx0 = fmaxf(mx0, __shfl_xor_sync(0xffffffffu, mx0, 2));
        mx1 = fmaxf(mx1, __shfl_xor_sync(0xffffffffu, mx1, 1));
        mx1 = fmaxf(mx1, __shfl_xor_sync(0xffffffffu, mx1, 2));

        const float sc0 = __expf(m0 - mx0);
        const float sc1 = __expf(m1 - mx1);
        m0 = mx0; m1 = mx1;

        float rs0 = 0.f, rs1 = 0.f;
        #pragma unroll
        for (int nb = 0; nb < 4; nb++) {
            s[nb][0] = ma[nb].x * __expf(s[nb][0] - mx0);
            s[nb][1] = ma[nb].y * __expf(s[nb][1] - mx0);
            s[nb][2] = mb[nb].x * __expf(s[nb][2] - mx1);
            s[nb][3] = mb[nb].y * __expf(s[nb][3] - mx1);
            rs0 += s[nb][0] + s[nb][1];
            rs1 += s[nb][2] + s[nb][3];
        }
        rs0 += __shfl_xor_sync(0xffffffffu, rs0, 1);
        rs0 += __shfl_xor_sync(0xffffffffu, rs0, 2);
        rs1 += __shfl_xor_sync(0xffffffffu, rs1, 1);
        rs1 += __shfl_xor_sync(0xffffffffu, rs1, 2);
        l0 = l0 * sc0 + rs0;
        l1 = l1 * sc1 + rs1;

        // --- unconditional rescale (branchless; sc==1 common and cheap) ---
        #pragma unroll
        for (int n = 0; n < 16; n++) {
            o[n][0] *= sc0; o[n][1] *= sc0; o[n][2] *= sc1; o[n][3] *= sc1;
        }

        // --- stage P (fp16, in [0,1]) to warp-private smem rows ---
        __syncwarp();
        #pragma unroll
        for (int nb = 0; nb < 4; nb++) {
            int col = nb * 8 + 2 * c;
            *(half2*)&Ph[rb * PS2 + col]       = __floats2half2_rn(s[nb][0], s[nb][1]);
            *(half2*)&Ph[(rb + 8) * PS2 + col] = __floats2half2_rn(s[nb][2], s[nb][3]);
        }
        __syncwarp();
        unsigned pa[2][4];
        {
            const uint32_t* p0 = (const uint32_t*)&Ph[rb * PS2];
            const uint32_t* p1 = (const uint32_t*)&Ph[(rb + 8) * PS2];
            #pragma unroll
            for (int ks = 0; ks < 2; ks++) {
                pa[ks][0] = p0[ks * 8 + c];
                pa[ks][1] = p1[ks * 8 + c];
                pa[ks][2] = p0[ks * 8 + c + 4];
                pa[ks][3] = p1[ks * 8 + c + 4];
            }
        }

        // --- O += P V ---
        const uint32_t vtile = sb + ((t & 1) ? SM_V1 : SM_V0);
        #pragma unroll
        for (int ks = 0; ks < 2; ks++) {
            #pragma unroll
            for (int nb2 = 0; nb2 < 8; nb2++) {
                unsigned b0, b1, b2, b3;
                LDSM_X4_T(b0, b1, b2, b3,
                          vtile + vbase + (uint32_t)(ks * 16 * (KS2 * 2) + nb2 * 32));
                mma_f16(o[nb2 * 2], pa[ks][0], pa[ks][1], pa[ks][2], pa[ks][3], b0, b1);
                mma_f16(o[nb2 * 2 + 1], pa[ks][0], pa[ks][1], pa[ks][2], pa[ks][3], b2, b3);
            }
        }

        CP_WAIT0();
        __syncthreads();
    }

    const float inv0 = 1.0f / l0, inv1 = 1.0f / l1;
    float* op = out + ((size_t)b * NN + gi) * HH;
    #pragma unroll
    for (int n = 0; n < 16; n++) {
        int col = n * 8 + 2 * c;
        float2 r0 = make_float2(o[n][0] * inv0, o[n][1] * inv0);
        float2 r1 = make_float2(o[n][2] * inv1, o[n][3] * inv1);
        *(float2*)&op[col] = r0;
        *(float2*)&op[8 * HH + col] = r1;
    }
}

extern "C" void kernel_launch(void* const* d_in, const int* in_sizes, int n_in,
                              void* d_out, int out_size) {
    const float* x    = (const float*)d_in[0];
    const float* mask = (const float*)d_in[1];
    const float* Wv   = (const float*)d_in[2];
    const float* bv   = (const float*)d_in[3];
    const float* Wk   = (const float*)d_in[4];
    const float* bk   = (const float*)d_in[5];
    const float* Wq   = (const float*)d_in[6];
    const float* bq   = (const float*)d_in[7];
    float* out = (float*)d_out;
    (void)in_sizes; (void)n_in; (void)out_size;

    cudaFuncSetAttribute(proj_kernel, cudaFuncAttributeMaxDynamicSharedMemorySize, PSM_TOTAL);
    proj_kernel<<<(BB * NN) / 64, 128, PSM_TOTAL>>>(x, Wv, bv, Wk, bk, Wq, bq);

    cudaFuncSetAttribute(attn_kernel, cudaFuncAttributeMaxDynamicSharedMemorySize, SM_TOTAL);
    attn_kernel<<<dim3(NN / 64, BB), 128, SM_TOTAL>>>(mask, out);
}